// round 2
// baseline (speedup 1.0000x reference)
#include <cuda_runtime.h>
#include <cstddef>

// HardDTW max-plus scan, warp-skewed pipeline (no per-step __syncthreads).
//
//   out[b,0,k] = x[b,0,k]
//   out[b,t,k] = x[b,t,k] + max(out[b,t-1,k], out[b,t-1,k-1])   (k-1 < 0 -> -inf)
//
// One CTA per batch (B=32). 256 threads; thread owns 4 consecutive k (float4
// carry in registers). Lane boundary via shfl_up. Warp boundary via a per-warp
// smem edge array (all T steps, 64KB dynamic smem) with a progress counter
// published once per CHUNK=16 steps (fence + volatile store). Consumer warps
// spin on the counter once per chunk, then run 16 steps barrier-free. Warps
// form a wavefront skewed 16 steps per warp level.

namespace {
constexpr int T = 2048;
constexpr int K = 1024;
constexpr int THREADS = 256;
constexpr int NWARP = THREADS / 32;        // 8
constexpr int RS = K / 4;                  // float4 per row = 256
constexpr int D = 8;                       // x prefetch depth (rolling)
constexpr int CHUNK = 16;                  // steps per sync epoch
constexpr size_t SMEM_BYTES =
    (size_t)NWARP * T * sizeof(float) + NWARP * sizeof(int);
}

__global__ __launch_bounds__(THREADS, 1)
void harddtw_pipe_kernel(const float* __restrict__ x, float* __restrict__ out) {
    extern __shared__ float smem[];
    float* ring = smem;                                    // [NWARP][T] edge values
    volatile int* cnt = (volatile int*)(smem + (size_t)NWARP * T);  // [NWARP]

    const int tid  = threadIdx.x;
    const int lane = tid & 31;
    const int warp = tid >> 5;
    const int b    = blockIdx.x;
    const float NEG_INF = __int_as_float(0xff800000);

    if (tid < NWARP) cnt[tid] = -1;
    __syncthreads();  // the only CTA-wide barrier

    const float4* __restrict__ xr =
        reinterpret_cast<const float4*>(x + (size_t)b * T * K) + tid;
    float4* __restrict__ orow =
        reinterpret_cast<float4*>(out + (size_t)b * T * K) + tid;

    const bool prod = (warp < NWARP - 1) && (lane == 31);
    float* myring = ring + (size_t)warp * T;
    const float* lring = ring + (size_t)(warp - 1) * T;    // valid only for warp>0

    // Row 0: out = x
    float4 cur = xr[0];
    orow[0] = cur;
    if (prod) myring[0] = cur.w;
    __threadfence_block();
    if (prod) cnt[warp] = 0;

    // Prefetch x rows 1..D
    float4 xq[D];
#pragma unroll
    for (int j = 0; j < D; ++j) xq[j] = xr[(size_t)(1 + j) * RS];

    for (int t0 = 1; t0 < T; t0 += CHUNK) {
        const int t_last = (t0 + CHUNK - 1 < T) ? (t0 + CHUNK - 1) : (T - 1);

        // Wait for upstream warp to have produced edges for steps t0-1..t_last-1
        float bv = NEG_INF;
        if (warp > 0) {
            const int need = t_last - 1;
            while (cnt[warp - 1] < need) { /* spin (volatile) */ }
            __threadfence_block();  // acquire: order ring loads after counter
            int idx = t0 - 1 + lane;
            if (idx > T - 2) idx = T - 2;   // clamp (values beyond t_last-1 unused)
            bv = lring[idx];
        }

#pragma unroll
        for (int j = 0; j < CHUNK; ++j) {
            const int t = t0 + j;
            if (t < T) {
                const float4 xv = xq[j & (D - 1)];
                const int tn = t + D;
                if (tn < T) xq[j & (D - 1)] = xr[(size_t)tn * RS];

                float up = __shfl_up_sync(0xffffffffu, cur.w, 1);
                const float bc = __shfl_sync(0xffffffffu, bv, j);
                if (lane == 0) up = (warp == 0) ? NEG_INF : bc;

                float4 n;
                n.x = xv.x + fmaxf(cur.x, up);
                n.y = xv.y + fmaxf(cur.y, cur.x);
                n.z = xv.z + fmaxf(cur.z, cur.y);
                n.w = xv.w + fmaxf(cur.w, cur.z);
                cur = n;

                orow[(size_t)t * RS] = n;
                if (prod) myring[t] = n.w;
            }
        }

        // Publish this chunk's edges
        __threadfence_block();
        if (prod) cnt[warp] = t_last;
    }
}

extern "C" void kernel_launch(void* const* d_in, const int* in_sizes, int n_in,
                              void* d_out, int out_size) {
    const float* x = (const float*)d_in[0];
    float* out = (float*)d_out;
    const int B = in_sizes[0] / (T * K);
    cudaFuncSetAttribute(harddtw_pipe_kernel,
                         cudaFuncAttributeMaxDynamicSharedMemorySize,
                         (int)SMEM_BYTES);
    harddtw_pipe_kernel<<<B, THREADS, SMEM_BYTES>>>(x, out);
}

// round 3
// speedup vs baseline: 4.5350x; 4.5350x over previous
#include <cuda_runtime.h>
#include <cstddef>

// HardDTW max-plus scan — chunk-skewed warp wavefront, 1 barrier per 16 steps.
//
//   out[b,0,k] = x[b,0,k]
//   out[b,t,k] = x[b,t,k] + max(out[b,t-1,k], out[b,t-1,k-1])   (k-1 < 0 -> -inf)
//
// One CTA per batch (B=32), 256 threads, thread owns 4 consecutive k (float4
// carry). Warp w processes chunk c = e - w (16 steps) at epoch e; one
// __syncthreads per epoch. Upstream edges (lane-31 cur.w of warp w-1) pass
// through a double-buffered smem array indexed by epoch parity. x prefetched
// with a rolling 16-deep float4 register queue (refilled one chunk ahead).

namespace {
constexpr int T = 2048;
constexpr int K = 1024;
constexpr int THREADS = 256;
constexpr int NWARP = THREADS / 32;          // 8
constexpr int RS = K / 4;                    // float4 per row
constexpr int CHUNK = 16;
constexpr int NCHUNK = T / CHUNK;            // 128
constexpr int NEPOCH = NCHUNK + NWARP - 1;   // 135
}

__global__ __launch_bounds__(THREADS, 1)
void harddtw_wave_kernel(const float* __restrict__ x, float* __restrict__ out) {
    // edges[p][w][j] : upstream boundary needed by warp w+1 at step t0+j of a
    // chunk, i.e. warp w's edge value at step t0+j-1 (slot 0 = last edge of
    // warp w's previous chunk).
    __shared__ float edges[2][NWARP][CHUNK];

    const int tid  = threadIdx.x;
    const int lane = tid & 31;
    const int warp = tid >> 5;
    const int b    = blockIdx.x;
    const float NEG_INF = __int_as_float(0xff800000);

    const float4* __restrict__ xr =
        reinterpret_cast<const float4*>(x + (size_t)b * T * K) + tid;
    float4* __restrict__ orow =
        reinterpret_cast<float4*>(out + (size_t)b * T * K) + tid;

    const bool prod = (warp < NWARP - 1) && (lane == 31);
    const int pw = (warp == 0) ? 0 : (warp - 1);   // safe upstream index
    const int bl = (lane < CHUNK) ? lane : (CHUNK - 1);

    // Preload chunk 0 (rows 0..15) into the rolling queue.
    float4 xq[CHUNK];
#pragma unroll
    for (int j = 0; j < CHUNK; ++j) xq[j] = xr[(size_t)j * RS];

    float4 cur = make_float4(NEG_INF, NEG_INF, NEG_INF, NEG_INF);

    for (int e = 0; e < NEPOCH; ++e) {
        const int c = e - warp;
        if (0 <= c && c < NCHUNK) {
            const int t0 = c * CHUNK;

            // Boundary vector from upstream warp (written during epoch e-1).
            float bv = edges[(e - 1) & 1][pw][bl];

            // Publish slot 0 for downstream: our edge at step t0-1
            // (end-of-previous-chunk carry; unused garbage when c == 0).
            if (prod) edges[e & 1][warp][0] = cur.w;

#pragma unroll
            for (int j = 0; j < CHUNK; ++j) {
                const int t = t0 + j;
                const float4 xv = xq[j];
                if (c + 1 < NCHUNK) xq[j] = xr[(size_t)(t + CHUNK) * RS];

                if (c == 0 && j == 0) {
                    cur = xv;  // init row: out[0] = x[0]
                } else {
                    float up = __shfl_up_sync(0xffffffffu, cur.w, 1);
                    const float bc = __shfl_sync(0xffffffffu, bv, j);
                    if (lane == 0) up = (warp == 0) ? NEG_INF : bc;

                    float4 n;
                    n.x = xv.x + fmaxf(cur.x, up);
                    n.y = xv.y + fmaxf(cur.y, cur.x);
                    n.z = xv.z + fmaxf(cur.z, cur.y);
                    n.w = xv.w + fmaxf(cur.w, cur.z);
                    cur = n;
                }

                orow[(size_t)t * RS] = cur;
                if (j < CHUNK - 1) {
                    if (prod) edges[e & 1][warp][j + 1] = cur.w;
                }
            }
        }
        __syncthreads();
    }
}

extern "C" void kernel_launch(void* const* d_in, const int* in_sizes, int n_in,
                              void* d_out, int out_size) {
    const float* x = (const float*)d_in[0];
    float* out = (float*)d_out;
    const int B = in_sizes[0] / (T * K);
    harddtw_wave_kernel<<<B, THREADS>>>(x, out);
}